// round 7
// baseline (speedup 1.0000x reference)
#include <cuda_runtime.h>
#include <math_constants.h>

// ROI max pooling: feature_map [B=2, H=38, W=38, C=512] f32, rois [B,N=64,4] i32 (y,x,h,w)
// output [B, N, 7, 7, C] f32.
//
// One block per (roi, cell): grid = B*N*49 = 6272 blocks, 128 threads,
// each thread owns one float4 of the 512 channels -> every pixel read is a
// fully-coalesced 2KB transaction per block. Cells partition the ROI exactly
// (h,w >= P), so each ROI pixel is read exactly once per ROI; cross-ROI reuse
// is served by L2 (feature map = 5.9 MB << 126 MB L2) and opportunistically L1
// via the read-only path.

#define B_ 2
#define N_ 64
#define H_ 38
#define W_ 38
#define C4_ 128   // C/4 = 512/4
#define P_ 7
#define PP_ 49

__global__ __launch_bounds__(128, 8)
void roi_pool_kernel(const float4* __restrict__ fm,
                     const int4* __restrict__ rois,
                     float4* __restrict__ out) {
    const int cell = blockIdx.x % PP_;
    const int roi  = blockIdx.x / PP_;          // roi = b*N + n
    const int b    = roi >> 6;                  // N = 64

    const int4 r = __ldg(&rois[roi]);           // (y0, x0, h, w)
    const int y0 = r.x, x0 = r.y, h = r.z, w = r.w;

    const int py = cell / P_;
    const int px = cell % P_;

    // bin [floor(py*h/P), floor((py+1)*h/P)) — identical to ref's (P*r + P-1)//h assignment
    const int ys = y0 + (py * h) / P_;
    const int ye = y0 + ((py + 1) * h) / P_;
    const int xs = x0 + (px * w) / P_;
    const int xe = x0 + ((px + 1) * w) / P_;

    const int c = threadIdx.x;                  // 0..127 (float4 channel index)

    float4 m0 = make_float4(-CUDART_INF_F, -CUDART_INF_F, -CUDART_INF_F, -CUDART_INF_F);
    float4 m1 = m0;

    #pragma unroll 1
    for (int y = ys; y < ye; ++y) {
        const float4* rowp = fm + ((size_t)(b * H_ + y) * W_) * C4_ + c;
        int x = xs;
        // two independent accumulators -> both LDG.128 issue back-to-back
        #pragma unroll 1
        for (; x + 1 < xe; x += 2) {
            float4 v0 = __ldg(rowp + (size_t)x * C4_);
            float4 v1 = __ldg(rowp + (size_t)(x + 1) * C4_);
            m0.x = fmaxf(m0.x, v0.x); m0.y = fmaxf(m0.y, v0.y);
            m0.z = fmaxf(m0.z, v0.z); m0.w = fmaxf(m0.w, v0.w);
            m1.x = fmaxf(m1.x, v1.x); m1.y = fmaxf(m1.y, v1.y);
            m1.z = fmaxf(m1.z, v1.z); m1.w = fmaxf(m1.w, v1.w);
        }
        if (x < xe) {
            float4 v0 = __ldg(rowp + (size_t)x * C4_);
            m0.x = fmaxf(m0.x, v0.x); m0.y = fmaxf(m0.y, v0.y);
            m0.z = fmaxf(m0.z, v0.z); m0.w = fmaxf(m0.w, v0.w);
        }
    }

    m0.x = fmaxf(m0.x, m1.x); m0.y = fmaxf(m0.y, m1.y);
    m0.z = fmaxf(m0.z, m1.z); m0.w = fmaxf(m0.w, m1.w);

    // out layout [B,N,7,7,C]: linear cell index == blockIdx.x
    out[(size_t)blockIdx.x * C4_ + c] = m0;
}

extern "C" void kernel_launch(void* const* d_in, const int* in_sizes, int n_in,
                              void* d_out, int out_size) {
    const float4* fm  = (const float4*)d_in[0];
    const int4* rois  = (const int4*)d_in[1];
    float4* out       = (float4*)d_out;

    dim3 grid(B_ * N_ * PP_);
    dim3 block(128);
    roi_pool_kernel<<<grid, block>>>(fm, rois, out);
}